// round 5
// baseline (speedup 1.0000x reference)
#include <cuda_runtime.h>

// SSIM loss, fused single pass + fused finalize. B=64, H=W=384, WIN=7.
//
// R5 (= R4 retry; infra failure last round): occupancy push. Rings for
// sx/sy/sxy live in a SMEM ring buffer (float2 per thread, 7 deep); sxx/syy
// rings stay in registers (static idx via the 7-row unroll). Dynamic smem
// (54.2KB/CTA), __launch_bounds__(192,3) -> 3 CTAs/SM (18 warps) vs 2 (12).

#define BATCH    64
#define HH       384
#define WW       384
#define WIN      7
#define OH       378
#define OW       378
#define NBANDS   9
#define OROWS    (OH / NBANDS)          // 42 output rows per band
#define INROWS   (OROWS + WIN - 1)      // 48 input rows per band
#define NTHREADS 192
#define ROWW     392                    // 384 data + 8 zero pad (reads to col 391)
#define NF4      (WW / 4)               // 96 float4 per row
#define NCTAS    (NBANDS * BATCH)       // 576

#define XB_BYTES   (WIN * ROWW * 4)             // 10976
#define RING_BYTES (3 * WIN * NTHREADS * 8)     // 32256
#define SMEM_BYTES (2 * XB_BYTES + RING_BYTES)  // 54208

__device__ float g_part[NCTAS];
__device__ unsigned int g_count;        // zero-init; last block resets to 0

__global__ __launch_bounds__(NTHREADS, 3) void ssim_main_kernel(
    const float* __restrict__ X, const float* __restrict__ Y,
    const float* __restrict__ data_range, float* __restrict__ out)
{
    extern __shared__ unsigned char dynsmem[];
    float (*xb)[ROWW] = (float (*)[ROWW])(dynsmem);
    float (*yb)[ROWW] = (float (*)[ROWW])(dynsmem + XB_BYTES);
    float2* ringbase  = (float2*)(dynsmem + 2 * XB_BYTES);
    float2* ring_sx  = ringbase;                         // [7][192]
    float2* ring_sy  = ringbase + WIN * NTHREADS;        // [7][192]
    float2* ring_sxy = ringbase + 2 * WIN * NTHREADS;    // [7][192]

    __shared__ float warpsum[NTHREADS / 32];
    __shared__ double dsum[NTHREADS / 32];
    __shared__ int is_last;

    const int t    = threadIdx.x;
    const int band = blockIdx.x;
    const int b    = blockIdx.y;
    const int row0 = band * OROWS;
    const int c    = 2 * t;

    const float L   = data_range[b];
    const float C1s = (0.49f * L) * (0.49f * L);     // C1 * 49^2
    const float C2s = (1.47f * L) * (1.47f * L);     // C2 * 49^2
    const float covn  = 49.0f / 48.0f;
    const float covn2 = 2.0f * covn;

    const float* __restrict__ Xb = X + (size_t)b * HH * WW;
    const float* __restrict__ Yb = Y + (size_t)b * HH * WW;

    // --- one-time init: zero smem rings (own slots) + pad columns 384..391 ---
    {
        const float2 z2 = make_float2(0.f, 0.f);
        for (int e = t; e < 3 * WIN * NTHREADS; e += NTHREADS) ringbase[e] = z2;
        for (int e = t; e < WIN * 8; e += NTHREADS) {
            const int rr = e >> 3;
            const int cc = 384 + (e & 7);
            xb[rr][cc] = 0.f;
            yb[rr][cc] = 0.f;
        }
    }

    // register rings for sxx/syy (static idx via unroll)
    float rxx0[WIN], rxx1[WIN], ryy0[WIN], ryy1[WIN];
#pragma unroll
    for (int i = 0; i < WIN; i++) { rxx0[i]=0.f; rxx1[i]=0.f; ryy0[i]=0.f; ryy1[i]=0.f; }

    float Wx0=0.f, Wx1=0.f, Wy0=0.f, Wy1=0.f;
    float Wxx0=0.f, Wxx1=0.f, Wxy0=0.f, Wxy1=0.f, Wyy0=0.f, Wyy1=0.f;
    float acc = 0.f;
    float pn = 0.f, pd = 1.f;
    bool  have = false;

    for (int r0 = 0; r0 < INROWS; r0 += WIN) {
        const int nrows = min(WIN, INROWS - r0);

        {
            const float4* __restrict__ Xr = (const float4*)(Xb + (size_t)(row0 + r0) * WW);
            const float4* __restrict__ Yr = (const float4*)(Yb + (size_t)(row0 + r0) * WW);
            const int total = nrows * NF4;
            for (int e = t; e < total; e += NTHREADS) {
                const int rr = e / NF4;
                const int cc = e - rr * NF4;
                *(float4*)&xb[rr][cc * 4] = Xr[e];
                *(float4*)&yb[rr][cc * 4] = Yr[e];
            }
        }
        __syncthreads();

#pragma unroll
        for (int i = 0; i < WIN; i++) {
            if (i < nrows) {
                float2 a0 = *(const float2*)&xb[i][c];
                float2 a1 = *(const float2*)&xb[i][c + 2];
                float2 a2 = *(const float2*)&xb[i][c + 4];
                float2 a3 = *(const float2*)&xb[i][c + 6];
                float2 b0 = *(const float2*)&yb[i][c];
                float2 b1 = *(const float2*)&yb[i][c + 2];
                float2 b2 = *(const float2*)&yb[i][c + 4];
                float2 b3 = *(const float2*)&yb[i][c + 6];
                const float x0=a0.x, x1=a0.y, x2=a1.x, x3=a1.y, x4=a2.x, x5=a2.y, x6=a3.x, x7=a3.y;
                const float y0=b0.x, y1=b0.y, y2=b1.x, y3=b1.y, y4=b2.x, y5=b2.y, y6=b3.x, y7=b3.y;

                // 7-tap sums, col0 direct, col1 via slide
                const float sx0 = ((x0+x1)+(x2+x3)) + ((x4+x5)+x6);
                const float sx1 = sx0 - x0 + x7;
                const float sy0 = ((y0+y1)+(y2+y3)) + ((y4+y5)+y6);
                const float sy1 = sy0 - y0 + y7;
                float sxx0 = x0*x0; sxx0=fmaf(x1,x1,sxx0); sxx0=fmaf(x2,x2,sxx0);
                sxx0=fmaf(x3,x3,sxx0); sxx0=fmaf(x4,x4,sxx0); sxx0=fmaf(x5,x5,sxx0); sxx0=fmaf(x6,x6,sxx0);
                const float sxx1 = sxx0 + fmaf(x7, x7, -(x0*x0));
                float sxy0 = x0*y0; sxy0=fmaf(x1,y1,sxy0); sxy0=fmaf(x2,y2,sxy0);
                sxy0=fmaf(x3,y3,sxy0); sxy0=fmaf(x4,y4,sxy0); sxy0=fmaf(x5,y5,sxy0); sxy0=fmaf(x6,y6,sxy0);
                const float sxy1 = sxy0 + fmaf(x7, y7, -(x0*y0));
                float syy0 = y0*y0; syy0=fmaf(y1,y1,syy0); syy0=fmaf(y2,y2,syy0);
                syy0=fmaf(y3,y3,syy0); syy0=fmaf(y4,y4,syy0); syy0=fmaf(y5,y5,syy0); syy0=fmaf(y6,y6,syy0);
                const float syy1 = syy0 + fmaf(y7, y7, -(y0*y0));

                // vertical running windows: smem rings for sx/sy/sxy
                {
                    const int ro = i * NTHREADS + t;
                    const float2 ox  = ring_sx[ro];
                    const float2 oy  = ring_sy[ro];
                    const float2 oxy = ring_sxy[ro];
                    Wx0  += sx0  - ox.x;   Wx1  += sx1  - ox.y;
                    Wy0  += sy0  - oy.x;   Wy1  += sy1  - oy.y;
                    Wxy0 += sxy0 - oxy.x;  Wxy1 += sxy1 - oxy.y;
                    ring_sx[ro]  = make_float2(sx0, sx1);
                    ring_sy[ro]  = make_float2(sy0, sy1);
                    ring_sxy[ro] = make_float2(sxy0, sxy1);
                }
                // register rings for sxx/syy
                Wxx0 += sxx0 - rxx0[i]; rxx0[i] = sxx0;
                Wxx1 += sxx1 - rxx1[i]; rxx1[i] = sxx1;
                Wyy0 += syy0 - ryy0[i]; ryy0[i] = syy0;
                Wyy1 += syy1 - ryy1[i]; ryy1[i] = syy1;

                const int r = r0 + i;
                if (r >= WIN - 1) {
                    // scale-free SSIM (x 49^2)
                    const float pxy0 = Wx0 * Wy0;
                    const float px20 = Wx0 * Wx0;
                    const float py20 = Wy0 * Wy0;
                    const float n1a = fmaf(2.0f, pxy0, C1s);
                    const float d1a = px20 + py20 + C1s;
                    const float n2a = fmaf(covn2, fmaf(49.0f, Wxy0, -pxy0), C2s);
                    const float d2a = fmaf(covn,
                        fmaf(49.0f, Wxx0, -px20) + fmaf(49.0f, Wyy0, -py20), C2s);
                    const float Na = n1a * n2a;
                    const float Da = d1a * d2a;
                    const float pxy1 = Wx1 * Wy1;
                    const float px21 = Wx1 * Wx1;
                    const float py21 = Wy1 * Wy1;
                    const float n1b = fmaf(2.0f, pxy1, C1s);
                    const float d1b = px21 + py21 + C1s;
                    const float n2b = fmaf(covn2, fmaf(49.0f, Wxy1, -pxy1), C2s);
                    const float d2b = fmaf(covn,
                        fmaf(49.0f, Wxx1, -px21) + fmaf(49.0f, Wyy1, -py21), C2s);
                    const float Nb = n1b * n2b;
                    const float Db = d1b * d2b;
                    // 2 cols -> one rational; pair rows -> 1 divide per 4 px
                    const float n2r = fmaf(Na, Db, Nb * Da);
                    const float d2r = Da * Db;
                    if (have) {
                        acc += __fdividef(fmaf(pn, d2r, n2r * pd), pd * d2r);
                        have = false;
                    } else {
                        pn = n2r; pd = d2r; have = true;
                    }
                }
            }
        }
        __syncthreads();
    }
    if (have) acc += __fdividef(pn, pd);
    if (c + 1 >= OW) acc = 0.f;   // threads 189..191 computed on pad garbage

    // block reduction -> per-CTA partial
#pragma unroll
    for (int o = 16; o > 0; o >>= 1)
        acc += __shfl_xor_sync(0xffffffffu, acc, o);
    if ((t & 31) == 0) warpsum[t >> 5] = acc;
    __syncthreads();
    const int cta = b * NBANDS + band;
    if (t == 0) {
        float s = 0.f;
#pragma unroll
        for (int w = 0; w < NTHREADS / 32; w++) s += warpsum[w];
        g_part[cta] = s;
        __threadfence();
        unsigned int n = atomicAdd(&g_count, 1u);
        is_last = (n == NCTAS - 1) ? 1 : 0;
    }
    __syncthreads();

    // last CTA: deterministic final reduction
    if (is_last) {
        __threadfence();
        double s = 0.0;
        s += (double)g_part[t];
        s += (double)g_part[t + NTHREADS];
        s += (double)g_part[t + 2 * NTHREADS];
#pragma unroll
        for (int o = 16; o > 0; o >>= 1)
            s += __shfl_xor_sync(0xffffffffu, s, o);
        if ((t & 31) == 0) dsum[t >> 5] = s;
        __syncthreads();
        if (t == 0) {
            double tot = 0.0;
#pragma unroll
            for (int w = 0; w < NTHREADS / 32; w++) tot += dsum[w];
            out[0] = (float)(1.0 - tot / ((double)BATCH * OH * OW));
            g_count = 0;   // reset for next graph replay
        }
    }
}

extern "C" void kernel_launch(void* const* d_in, const int* in_sizes, int n_in,
                              void* d_out, int out_size)
{
    const float* X  = (const float*)d_in[0];
    const float* Y  = (const float*)d_in[1];
    const float* dr = (const float*)d_in[2];
    float* out = (float*)d_out;

    (void)cudaFuncSetAttribute(ssim_main_kernel,
                               cudaFuncAttributeMaxDynamicSharedMemorySize,
                               SMEM_BYTES);
    dim3 grid(NBANDS, BATCH);
    ssim_main_kernel<<<grid, NTHREADS, SMEM_BYTES>>>(X, Y, dr, out);
}

// round 8
// speedup vs baseline: 1.6491x; 1.6491x over previous
#include <cuda_runtime.h>

// SSIM loss, fused single pass + fused finalize. B=64, H=W=384, WIN=7.
//
// R6: revert smem rings (R5 regression). Algebraic state compression:
// track u=x+y, v=x-y streams; SSIM needs only {Su, Sv, Suu, Svv} windows
// (SxSy, Sx^2+Sy^2, Sxy, Sxx+Syy all derive from them). Ring: 4 stats x
// 2 cols x 7 deep = 56 regs (was 70); staging converts to u,v so x,y never
// live in the hot loop. launch_bounds(192,3) -> target 18 warps/SM.
// First/last steps peeled: middle 5 steps have no per-row predicates.

#define BATCH    64
#define HH       384
#define WW       384
#define WIN      7
#define OH       378
#define OW       378
#define NBANDS   9
#define OROWS    42                     // output rows per band
#define INROWS   48                     // input rows per band
#define NTHREADS 192
#define ROWW     392                    // 384 data + 8 zero pad
#define NF4      (WW / 4)               // 96
#define NCTAS    (NBANDS * BATCH)       // 576

__device__ float g_part[NCTAS];
__device__ unsigned int g_count;        // zero-init; last block resets to 0

__global__ __launch_bounds__(NTHREADS, 3) void ssim_main_kernel(
    const float* __restrict__ X, const float* __restrict__ Y,
    const float* __restrict__ data_range, float* __restrict__ out)
{
    __shared__ float ub[WIN][ROWW];
    __shared__ float vb[WIN][ROWW];
    __shared__ float warpsum[NTHREADS / 32];
    __shared__ double dsum[NTHREADS / 32];
    __shared__ int is_last;

    const int t    = threadIdx.x;
    const int band = blockIdx.x;
    const int b    = blockIdx.y;
    const int row0 = band * OROWS;
    const int c    = 2 * t;

    const float L    = data_range[b];
    const float C1s  = (0.49f * L) * (0.49f * L);    // C1 * 49^2
    const float C2s  = (1.47f * L) * (1.47f * L);    // C2 * 49^2
    const float ch   = 0.5f;
    const float cvh  = 0.5f * (49.0f / 48.0f);       // covn/2

    const float* __restrict__ Xb = X + (size_t)b * HH * WW;
    const float* __restrict__ Yb = Y + (size_t)b * HH * WW;

    // zero pad columns 384..391 (written once; staging never touches them)
    for (int e = t; e < WIN * 8; e += NTHREADS) {
        const int rr = e >> 3;
        const int cc = 384 + (e & 7);
        ub[rr][cc] = 0.f;
        vb[rr][cc] = 0.f;
    }

    // rings: 4 stats x 2 cols x 7 (static idx via unroll)
    float ru0[WIN], ru1[WIN], rv0[WIN], rv1[WIN];
    float ruu0[WIN], ruu1[WIN], rvv0[WIN], rvv1[WIN];
#pragma unroll
    for (int i = 0; i < WIN; i++) {
        ru0[i]=0.f; ru1[i]=0.f; rv0[i]=0.f; rv1[i]=0.f;
        ruu0[i]=0.f; ruu1[i]=0.f; rvv0[i]=0.f; rvv1[i]=0.f;
    }
    float Wu0=0.f, Wu1=0.f, Wv0=0.f, Wv1=0.f;
    float Wuu0=0.f, Wuu1=0.f, Wvv0=0.f, Wvv1=0.f;
    float acc = 0.f;
    float pn = 0.f, pd = 1.f;
    bool  have = false;

    // ---- stage nrows rows, converting (x,y) -> (u,v) ----
    auto stage = [&](int r0, int nrows) {
        const float4* __restrict__ Xr = (const float4*)(Xb + (size_t)(row0 + r0) * WW);
        const float4* __restrict__ Yr = (const float4*)(Yb + (size_t)(row0 + r0) * WW);
        const int total = nrows * NF4;
        for (int e = t; e < total; e += NTHREADS) {
            const int rr = e / NF4;
            const int cc = (e - rr * NF4) * 4;
            const float4 xv = Xr[e];
            const float4 yv = Yr[e];
            float4 uu, vv;
            uu.x = xv.x + yv.x; vv.x = xv.x - yv.x;
            uu.y = xv.y + yv.y; vv.y = xv.y - yv.y;
            uu.z = xv.z + yv.z; vv.z = xv.z - yv.z;
            uu.w = xv.w + yv.w; vv.w = xv.w - yv.w;
            *(float4*)&ub[rr][cc] = uu;
            *(float4*)&vb[rr][cc] = vv;
        }
    };

    // ---- process one staged row; i compile-time, emit compile-time ----
    auto dorow = [&](int i, bool emit) {
        float2 a0 = *(const float2*)&ub[i][c];
        float2 a1 = *(const float2*)&ub[i][c + 2];
        float2 a2 = *(const float2*)&ub[i][c + 4];
        float2 a3 = *(const float2*)&ub[i][c + 6];
        float2 b0 = *(const float2*)&vb[i][c];
        float2 b1 = *(const float2*)&vb[i][c + 2];
        float2 b2 = *(const float2*)&vb[i][c + 4];
        float2 b3 = *(const float2*)&vb[i][c + 6];
        const float u0=a0.x, u1=a0.y, u2=a1.x, u3=a1.y, u4=a2.x, u5=a2.y, u6=a3.x, u7=a3.y;
        const float v0=b0.x, v1=b0.y, v2=b1.x, v3=b1.y, v4=b2.x, v5=b2.y, v6=b3.x, v7=b3.y;

        const float su0 = ((u0+u1)+(u2+u3)) + ((u4+u5)+u6);
        const float su1 = (su0 - u0) + u7;
        const float sv0 = ((v0+v1)+(v2+v3)) + ((v4+v5)+v6);
        const float sv1 = (sv0 - v0) + v7;
        float suu0 = u0*u0; suu0=fmaf(u1,u1,suu0); suu0=fmaf(u2,u2,suu0);
        suu0=fmaf(u3,u3,suu0); suu0=fmaf(u4,u4,suu0); suu0=fmaf(u5,u5,suu0); suu0=fmaf(u6,u6,suu0);
        const float suu1 = fmaf(u7, u7, fmaf(-u0, u0, suu0));
        float svv0 = v0*v0; svv0=fmaf(v1,v1,svv0); svv0=fmaf(v2,v2,svv0);
        svv0=fmaf(v3,v3,svv0); svv0=fmaf(v4,v4,svv0); svv0=fmaf(v5,v5,svv0); svv0=fmaf(v6,v6,svv0);
        const float svv1 = fmaf(v7, v7, fmaf(-v0, v0, svv0));

        Wu0  += su0  - ru0[i];  ru0[i]  = su0;
        Wu1  += su1  - ru1[i];  ru1[i]  = su1;
        Wv0  += sv0  - rv0[i];  rv0[i]  = sv0;
        Wv1  += sv1  - rv1[i];  rv1[i]  = sv1;
        Wuu0 += suu0 - ruu0[i]; ruu0[i] = suu0;
        Wuu1 += suu1 - ruu1[i]; ruu1[i] = suu1;
        Wvv0 += svv0 - rvv0[i]; rvv0[i] = svv0;
        Wvv1 += svv1 - rvv1[i]; rvv1[i] = svv1;

        if (emit) {
            // col 0: A=Wu^2, B=Wv^2
            const float A0 = Wu0 * Wu0;
            const float B0 = Wv0 * Wv0;
            const float amb0 = A0 - B0;
            const float apb0 = A0 + B0;
            const float dmm0 = Wuu0 - Wvv0;
            const float dpp0 = Wuu0 + Wvv0;
            const float N1a = fmaf(ch, amb0, C1s);               // 2SxSy + C1s
            const float D1a = fmaf(ch, apb0, C1s);               // Sx^2+Sy^2 + C1s
            const float N2a = fmaf(cvh, fmaf(49.0f, dmm0, -amb0), C2s);
            const float D2a = fmaf(cvh, fmaf(49.0f, dpp0, -apb0), C2s);
            const float Na = N1a * N2a;
            const float Da = D1a * D2a;
            // col 1
            const float A1 = Wu1 * Wu1;
            const float B1 = Wv1 * Wv1;
            const float amb1 = A1 - B1;
            const float apb1 = A1 + B1;
            const float dmm1 = Wuu1 - Wvv1;
            const float dpp1 = Wuu1 + Wvv1;
            const float N1b = fmaf(ch, amb1, C1s);
            const float D1b = fmaf(ch, apb1, C1s);
            const float N2b = fmaf(cvh, fmaf(49.0f, dmm1, -amb1), C2s);
            const float D2b = fmaf(cvh, fmaf(49.0f, dpp1, -apb1), C2s);
            const float Nb = N1b * N2b;
            const float Db = D1b * D2b;
            // 2 cols -> one rational; pair rows -> 1 divide per 4 px
            const float n2r = fmaf(Na, Db, Nb * Da);
            const float d2r = Da * Db;
            if (have) {
                acc += __fdividef(fmaf(pn, d2r, n2r * pd), pd * d2r);
                have = false;
            } else {
                pn = n2r; pd = d2r; have = true;
            }
        }
    };

    // step 0: rows 0..6, only row 6 emits
    stage(0, WIN);
    __syncthreads();
#pragma unroll
    for (int i = 0; i < WIN; i++) dorow(i, i == WIN - 1);
    __syncthreads();

    // steps 1..5: full 7-row steps, all emit, no predicates
    for (int s = 1; s < 6; s++) {
        stage(s * WIN, WIN);
        __syncthreads();
#pragma unroll
        for (int i = 0; i < WIN; i++) dorow(i, true);
        __syncthreads();
    }

    // step 6: rows 42..47 (6 rows), all emit
    stage(6 * WIN, INROWS - 6 * WIN);
    __syncthreads();
#pragma unroll
    for (int i = 0; i < 6; i++) dorow(i, true);

    if (have) acc += __fdividef(pn, pd);
    if (c + 1 >= OW) acc = 0.f;   // threads 189..191: pad garbage

    // block reduction -> per-CTA partial
#pragma unroll
    for (int o = 16; o > 0; o >>= 1)
        acc += __shfl_xor_sync(0xffffffffu, acc, o);
    if ((t & 31) == 0) warpsum[t >> 5] = acc;
    __syncthreads();
    const int cta = b * NBANDS + band;
    if (t == 0) {
        float s = 0.f;
#pragma unroll
        for (int w = 0; w < NTHREADS / 32; w++) s += warpsum[w];
        g_part[cta] = s;
        __threadfence();
        unsigned int n = atomicAdd(&g_count, 1u);
        is_last = (n == NCTAS - 1) ? 1 : 0;
    }
    __syncthreads();

    // last CTA: deterministic final reduction
    if (is_last) {
        __threadfence();
        double s = 0.0;
        s += (double)g_part[t];
        s += (double)g_part[t + NTHREADS];
        s += (double)g_part[t + 2 * NTHREADS];
#pragma unroll
        for (int o = 16; o > 0; o >>= 1)
            s += __shfl_xor_sync(0xffffffffu, s, o);
        if ((t & 31) == 0) dsum[t >> 5] = s;
        __syncthreads();
        if (t == 0) {
            double tot = 0.0;
#pragma unroll
            for (int w = 0; w < NTHREADS / 32; w++) tot += dsum[w];
            out[0] = (float)(1.0 - tot / ((double)BATCH * OH * OW));
            g_count = 0;   // reset for next graph replay
        }
    }
}

extern "C" void kernel_launch(void* const* d_in, const int* in_sizes, int n_in,
                              void* d_out, int out_size)
{
    const float* X  = (const float*)d_in[0];
    const float* Y  = (const float*)d_in[1];
    const float* dr = (const float*)d_in[2];
    float* out = (float*)d_out;

    dim3 grid(NBANDS, BATCH);
    ssim_main_kernel<<<grid, NTHREADS>>>(X, Y, dr, out);
}

// round 9
// speedup vs baseline: 2.0435x; 1.2391x over previous
#include <cuda_runtime.h>
#include <cuda_pipeline_primitives.h>

// SSIM loss, fused single pass + fused finalize. B=64, H=W=384, WIN=7.
//
// R9: cp.async double-buffered staging. Tiles hold raw x,y (LDGSTS cannot
// transform); u=x+y, v=x-v computed inline in the hot row. Register rings
// keep the compressed 4-stat u,v form (56 regs). Step s+2's copy is issued
// after compute(s) and completes during compute(s+1) -> LDG latency off the
// critical path. NBANDS=7 -> 448 CTAs ~= one full wave at 3 CTAs/SM.

#define BATCH    64
#define HH       384
#define WW       384
#define WIN      7
#define OH       378
#define OW       378
#define NBANDS   7
#define OROWS    54                     // output rows per band
#define INROWS   60                     // input rows per band (54+6)
#define NTHREADS 192
#define ROWW     392                    // 384 data + 8 pad floats
#define NF4      (WW / 4)               // 96 16B chunks per row
#define NCTAS    (NBANDS * BATCH)       // 448

__device__ float g_part[NCTAS];
__device__ unsigned int g_count;        // zero-init; last block resets to 0

__global__ __launch_bounds__(NTHREADS, 3) void ssim_main_kernel(
    const float* __restrict__ X, const float* __restrict__ Y,
    const float* __restrict__ data_range, float* __restrict__ out)
{
    __shared__ float xb[2][WIN][ROWW];
    __shared__ float yb[2][WIN][ROWW];
    __shared__ float warpsum[NTHREADS / 32];
    __shared__ double dsum[NTHREADS / 32];
    __shared__ int is_last;

    const int t    = threadIdx.x;
    const int band = blockIdx.x;
    const int b    = blockIdx.y;
    const int row0 = band * OROWS;
    const int c    = 2 * t;

    const float L    = data_range[b];
    const float C1s  = (0.49f * L) * (0.49f * L);    // C1 * 49^2
    const float C2s  = (1.47f * L) * (1.47f * L);    // C2 * 49^2
    const float ch   = 0.5f;
    const float cvh  = 0.5f * (49.0f / 48.0f);       // covn/2

    const float* __restrict__ Xb = X + (size_t)b * HH * WW;
    const float* __restrict__ Yb = Y + (size_t)b * HH * WW;

    // rings: 4 stats x 2 cols x 7 (static idx via unroll)
    float ru0[WIN], ru1[WIN], rv0[WIN], rv1[WIN];
    float ruu0[WIN], ruu1[WIN], rvv0[WIN], rvv1[WIN];
#pragma unroll
    for (int i = 0; i < WIN; i++) {
        ru0[i]=0.f; ru1[i]=0.f; rv0[i]=0.f; rv1[i]=0.f;
        ruu0[i]=0.f; ruu1[i]=0.f; rvv0[i]=0.f; rvv1[i]=0.f;
    }
    float Wu0=0.f, Wu1=0.f, Wv0=0.f, Wv1=0.f;
    float Wuu0=0.f, Wuu1=0.f, Wvv0=0.f, Wvv1=0.f;
    float acc = 0.f;
    float pn = 0.f, pd = 1.f;
    bool  have = false;

    // ---- async-stage nrows rows of X,Y into buffer bi (raw, 16B chunks) ----
    auto stage = [&](int bi, int r0, int nrows) {
        const float* __restrict__ Xr = Xb + (size_t)(row0 + r0) * WW;
        const float* __restrict__ Yr = Yb + (size_t)(row0 + r0) * WW;
        const int total = nrows * NF4;
        for (int e = t; e < total; e += NTHREADS) {
            const int rr = e / NF4;
            const int cc = (e - rr * NF4) * 4;
            __pipeline_memcpy_async(&xb[bi][rr][cc], Xr + rr * WW + cc, 16);
            __pipeline_memcpy_async(&yb[bi][rr][cc], Yr + rr * WW + cc, 16);
        }
        __pipeline_commit();
    };

    // ---- process one staged row (raw x,y -> inline u,v) ----
    auto dorow = [&](int bi, int i, bool emit) {
        const float2 a0 = *(const float2*)&xb[bi][i][c];
        const float2 a1 = *(const float2*)&xb[bi][i][c + 2];
        const float2 a2 = *(const float2*)&xb[bi][i][c + 4];
        const float2 a3 = *(const float2*)&xb[bi][i][c + 6];
        const float2 b0 = *(const float2*)&yb[bi][i][c];
        const float2 b1 = *(const float2*)&yb[bi][i][c + 2];
        const float2 b2 = *(const float2*)&yb[bi][i][c + 4];
        const float2 b3 = *(const float2*)&yb[bi][i][c + 6];
        const float u0 = a0.x + b0.x, v0 = a0.x - b0.x;
        const float u1 = a0.y + b0.y, v1 = a0.y - b0.y;
        const float u2 = a1.x + b1.x, v2 = a1.x - b1.x;
        const float u3 = a1.y + b1.y, v3 = a1.y - b1.y;
        const float u4 = a2.x + b2.x, v4 = a2.x - b2.x;
        const float u5 = a2.y + b2.y, v5 = a2.y - b2.y;
        const float u6 = a3.x + b3.x, v6 = a3.x - b3.x;
        const float u7 = a3.y + b3.y, v7 = a3.y - b3.y;

        const float su0 = ((u0+u1)+(u2+u3)) + ((u4+u5)+u6);
        const float su1 = (su0 - u0) + u7;
        const float sv0 = ((v0+v1)+(v2+v3)) + ((v4+v5)+v6);
        const float sv1 = (sv0 - v0) + v7;
        float suu0 = u0*u0; suu0=fmaf(u1,u1,suu0); suu0=fmaf(u2,u2,suu0);
        suu0=fmaf(u3,u3,suu0); suu0=fmaf(u4,u4,suu0); suu0=fmaf(u5,u5,suu0); suu0=fmaf(u6,u6,suu0);
        const float suu1 = fmaf(u7, u7, fmaf(-u0, u0, suu0));
        float svv0 = v0*v0; svv0=fmaf(v1,v1,svv0); svv0=fmaf(v2,v2,svv0);
        svv0=fmaf(v3,v3,svv0); svv0=fmaf(v4,v4,svv0); svv0=fmaf(v5,v5,svv0); svv0=fmaf(v6,v6,svv0);
        const float svv1 = fmaf(v7, v7, fmaf(-v0, v0, svv0));

        Wu0  += su0  - ru0[i];  ru0[i]  = su0;
        Wu1  += su1  - ru1[i];  ru1[i]  = su1;
        Wv0  += sv0  - rv0[i];  rv0[i]  = sv0;
        Wv1  += sv1  - rv1[i];  rv1[i]  = sv1;
        Wuu0 += suu0 - ruu0[i]; ruu0[i] = suu0;
        Wuu1 += suu1 - ruu1[i]; ruu1[i] = suu1;
        Wvv0 += svv0 - rvv0[i]; rvv0[i] = svv0;
        Wvv1 += svv1 - rvv1[i]; rvv1[i] = svv1;

        if (emit) {
            const float A0 = Wu0 * Wu0;
            const float B0 = Wv0 * Wv0;
            const float amb0 = A0 - B0;
            const float apb0 = A0 + B0;
            const float dmm0 = Wuu0 - Wvv0;
            const float dpp0 = Wuu0 + Wvv0;
            const float N1a = fmaf(ch, amb0, C1s);
            const float D1a = fmaf(ch, apb0, C1s);
            const float N2a = fmaf(cvh, fmaf(49.0f, dmm0, -amb0), C2s);
            const float D2a = fmaf(cvh, fmaf(49.0f, dpp0, -apb0), C2s);
            const float Na = N1a * N2a;
            const float Da = D1a * D2a;
            const float A1 = Wu1 * Wu1;
            const float B1 = Wv1 * Wv1;
            const float amb1 = A1 - B1;
            const float apb1 = A1 + B1;
            const float dmm1 = Wuu1 - Wvv1;
            const float dpp1 = Wuu1 + Wvv1;
            const float N1b = fmaf(ch, amb1, C1s);
            const float D1b = fmaf(ch, apb1, C1s);
            const float N2b = fmaf(cvh, fmaf(49.0f, dmm1, -amb1), C2s);
            const float D2b = fmaf(cvh, fmaf(49.0f, dpp1, -apb1), C2s);
            const float Nb = N1b * N2b;
            const float Db = D1b * D2b;
            const float n2r = fmaf(Na, Db, Nb * Da);
            const float d2r = Da * Db;
            if (have) {
                acc += __fdividef(fmaf(pn, d2r, n2r * pd), pd * d2r);
                have = false;
            } else {
                pn = n2r; pd = d2r; have = true;
            }
        }
    };

    // ---- prologue: stage steps 0 and 1 ----
    stage(0, 0, WIN);
    stage(1, WIN, WIN);

    // step 0: rows 0..6, only row 6 emits; then prefetch step 2
    __pipeline_wait_prior(1);
    __syncthreads();
#pragma unroll
    for (int i = 0; i < WIN; i++) dorow(0, i, i == WIN - 1);
    __syncthreads();
    stage(0, 2 * WIN, WIN);

    // steps 1..6: full steps, all emit; prefetch step s+2
    for (int s = 1; s < 7; s++) {
        const int bi = s & 1;
        __pipeline_wait_prior(1);
        __syncthreads();
#pragma unroll
        for (int i = 0; i < WIN; i++) dorow(bi, i, true);
        __syncthreads();
        if (s + 2 <= 8)
            stage(bi, (s + 2) * WIN, (s + 2 == 8) ? (INROWS - 8 * WIN) : WIN);
    }

    // step 7: full, from buf1; nothing more to stage
    __pipeline_wait_prior(1);
    __syncthreads();
#pragma unroll
    for (int i = 0; i < WIN; i++) dorow(1, i, true);
    __syncthreads();

    // step 8: rows 56..59 (4 rows, ring slots 0..3), from buf0
    __pipeline_wait_prior(0);
    __syncthreads();
#pragma unroll
    for (int i = 0; i < 4; i++) dorow(0, i, true);

    if (have) acc += __fdividef(pn, pd);
    if (c + 1 >= OW) acc = 0.f;   // threads 189..191: pad garbage (incl. NaN) discarded

    // block reduction -> per-CTA partial
#pragma unroll
    for (int o = 16; o > 0; o >>= 1)
        acc += __shfl_xor_sync(0xffffffffu, acc, o);
    if ((t & 31) == 0) warpsum[t >> 5] = acc;
    __syncthreads();
    const int cta = b * NBANDS + band;
    if (t == 0) {
        float s = 0.f;
#pragma unroll
        for (int w = 0; w < NTHREADS / 32; w++) s += warpsum[w];
        g_part[cta] = s;
        __threadfence();
        unsigned int n = atomicAdd(&g_count, 1u);
        is_last = (n == NCTAS - 1) ? 1 : 0;
    }
    __syncthreads();

    // last CTA: deterministic final reduction (448 = 192 + 192 + 64)
    if (is_last) {
        __threadfence();
        double s = 0.0;
        s += (double)g_part[t];
        s += (double)g_part[t + NTHREADS];
        if (t < NCTAS - 2 * NTHREADS) s += (double)g_part[t + 2 * NTHREADS];
#pragma unroll
        for (int o = 16; o > 0; o >>= 1)
            s += __shfl_xor_sync(0xffffffffu, s, o);
        if ((t & 31) == 0) dsum[t >> 5] = s;
        __syncthreads();
        if (t == 0) {
            double tot = 0.0;
#pragma unroll
            for (int w = 0; w < NTHREADS / 32; w++) tot += dsum[w];
            out[0] = (float)(1.0 - tot / ((double)BATCH * OH * OW));
            g_count = 0;   // reset for next graph replay
        }
    }
}

extern "C" void kernel_launch(void* const* d_in, const int* in_sizes, int n_in,
                              void* d_out, int out_size)
{
    const float* X  = (const float*)d_in[0];
    const float* Y  = (const float*)d_in[1];
    const float* dr = (const float*)d_in[2];
    float* out = (float*)d_out;

    dim3 grid(NBANDS, BATCH);
    ssim_main_kernel<<<grid, NTHREADS>>>(X, Y, dr, out);
}